// round 13
// baseline (speedup 1.0000x reference)
#include <cuda_runtime.h>
#include <cstdint>

// LSTMDecoder: B=1024, A=H=16, R=128, T=128.
// R12: 2 batch elements per thread (ILP). Each thread owns hidden index j for
// batches b and b+512; the two independent LSTM chains interleave, so one
// chain's dependency stalls (~70% of cycles at 1 chain/thread) execute the
// other chain's instructions. Weights shared between the two chains.
// 8192 threads = 128 blocks x 64. Broadcast: sync-free SMEM (validated R8).
// Gate dots: fma.rn.f32x2, folded sigmoid 0.5-scale, even/odd split chains.

#define NT 128

__device__ __forceinline__ float tanhapx(float x) {
    float r;
    asm("tanh.approx.f32 %0, %1;" : "=f"(r) : "f"(x));
    return r;
}
__device__ __forceinline__ uint64_t pack2(float lo, float hi) {
    uint64_t r;
    asm("mov.b64 %0, {%1, %2};" : "=l"(r) : "f"(lo), "f"(hi));
    return r;
}
__device__ __forceinline__ void unpack2(float& lo, float& hi, uint64_t v) {
    asm("mov.b64 {%0, %1}, %2;" : "=f"(lo), "=f"(hi) : "l"(v));
}
__device__ __forceinline__ uint64_t fma2v(uint64_t a, uint64_t b, uint64_t c) {
    uint64_t d;
    asm("fma.rn.f32x2 %0, %1, %2, %3;" : "=l"(d) : "l"(a), "l"(b), "l"(c));
    return d;
}
__device__ __forceinline__ uint64_t add2(uint64_t a, uint64_t b) {
    uint64_t r;
    asm("add.rn.f32x2 %0, %1, %2;" : "=l"(r) : "l"(a), "l"(b));
    return r;
}

// One doubled LSTM cell: batches A and B interleaved. STS/LDS pinned in
// program order (per-warp in-order MIO => STS visible to later LDS, no sync);
// all arithmetic is non-volatile so ptxas interleaves the two chains.
#define CELL2(XVA, XVB) do {                                                  \
    asm volatile("st.shared.f32 [%0], %1;" :: "r"(wrA), "f"(hA) : "memory");  \
    asm volatile("st.shared.f32 [%0], %1;" :: "r"(wrB), "f"(hB) : "memory");  \
    uint64_t xdA = pack2((XVA), (XVA)), xdB = pack2((XVB), (XVB));            \
    uint64_t aiA0 = fma2v(xdA, wxi, bvi), agA0 = fma2v(xdA, wxg, bvg);        \
    uint64_t afA0 = fma2v(xdA, wxf, bvf), aoA0 = fma2v(xdA, wxo, bvo);        \
    uint64_t aiB0 = fma2v(xdB, wxi, bvi), agB0 = fma2v(xdB, wxg, bvg);        \
    uint64_t afB0 = fma2v(xdB, wxf, bvf), aoB0 = fma2v(xdB, wxo, bvo);        \
    uint64_t qA0,qA1,qA2,qA3,qA4,qA5,qA6,qA7;                                 \
    uint64_t qB0,qB1,qB2,qB3,qB4,qB5,qB6,qB7;                                 \
    asm volatile("ld.shared.v2.u64 {%0,%1},[%2];"                             \
                 : "=l"(qA0), "=l"(qA1) : "r"(rdA)      : "memory");          \
    asm volatile("ld.shared.v2.u64 {%0,%1},[%2];"                             \
                 : "=l"(qA2), "=l"(qA3) : "r"(rdA + 16) : "memory");          \
    asm volatile("ld.shared.v2.u64 {%0,%1},[%2];"                             \
                 : "=l"(qA4), "=l"(qA5) : "r"(rdA + 32) : "memory");          \
    asm volatile("ld.shared.v2.u64 {%0,%1},[%2];"                             \
                 : "=l"(qA6), "=l"(qA7) : "r"(rdA + 48) : "memory");          \
    asm volatile("ld.shared.v2.u64 {%0,%1},[%2];"                             \
                 : "=l"(qB0), "=l"(qB1) : "r"(rdB)      : "memory");          \
    asm volatile("ld.shared.v2.u64 {%0,%1},[%2];"                             \
                 : "=l"(qB2), "=l"(qB3) : "r"(rdB + 16) : "memory");          \
    asm volatile("ld.shared.v2.u64 {%0,%1},[%2];"                             \
                 : "=l"(qB4), "=l"(qB5) : "r"(rdB + 32) : "memory");          \
    asm volatile("ld.shared.v2.u64 {%0,%1},[%2];"                             \
                 : "=l"(qB6), "=l"(qB7) : "r"(rdB + 48) : "memory");          \
    uint64_t aiA1, afA1, agA1, aoA1, aiB1, afB1, agB1, aoB1;                  \
    aiA0 = fma2v(qA0, Wi[0], aiA0);  aiA1 = fma2v(qA1, Wi[1], 0ull);          \
    agA0 = fma2v(qA0, Wg[0], agA0);  agA1 = fma2v(qA1, Wg[1], 0ull);          \
    afA0 = fma2v(qA0, Wf[0], afA0);  afA1 = fma2v(qA1, Wf[1], 0ull);          \
    aoA0 = fma2v(qA0, Wo[0], aoA0);  aoA1 = fma2v(qA1, Wo[1], 0ull);          \
    aiB0 = fma2v(qB0, Wi[0], aiB0);  aiB1 = fma2v(qB1, Wi[1], 0ull);          \
    agB0 = fma2v(qB0, Wg[0], agB0);  agB1 = fma2v(qB1, Wg[1], 0ull);          \
    afB0 = fma2v(qB0, Wf[0], afB0);  afB1 = fma2v(qB1, Wf[1], 0ull);          \
    aoB0 = fma2v(qB0, Wo[0], aoB0);  aoB1 = fma2v(qB1, Wo[1], 0ull);          \
    aiA0 = fma2v(qA2, Wi[2], aiA0);  aiA1 = fma2v(qA3, Wi[3], aiA1);          \
    agA0 = fma2v(qA2, Wg[2], agA0);  agA1 = fma2v(qA3, Wg[3], agA1);          \
    afA0 = fma2v(qA2, Wf[2], afA0);  afA1 = fma2v(qA3, Wf[3], afA1);          \
    aoA0 = fma2v(qA2, Wo[2], aoA0);  aoA1 = fma2v(qA3, Wo[3], aoA1);          \
    aiB0 = fma2v(qB2, Wi[2], aiB0);  aiB1 = fma2v(qB3, Wi[3], aiB1);          \
    agB0 = fma2v(qB2, Wg[2], agB0);  agB1 = fma2v(qB3, Wg[3], agB1);          \
    afB0 = fma2v(qB2, Wf[2], afB0);  afB1 = fma2v(qB3, Wf[3], afB1);          \
    aoB0 = fma2v(qB2, Wo[2], aoB0);  aoB1 = fma2v(qB3, Wo[3], aoB1);          \
    aiA0 = fma2v(qA4, Wi[4], aiA0);  aiA1 = fma2v(qA5, Wi[5], aiA1);          \
    agA0 = fma2v(qA4, Wg[4], agA0);  agA1 = fma2v(qA5, Wg[5], agA1);          \
    afA0 = fma2v(qA4, Wf[4], afA0);  afA1 = fma2v(qA5, Wf[5], afA1);          \
    aoA0 = fma2v(qA4, Wo[4], aoA0);  aoA1 = fma2v(qA5, Wo[5], aoA1);          \
    aiB0 = fma2v(qB4, Wi[4], aiB0);  aiB1 = fma2v(qB5, Wi[5], aiB1);          \
    agB0 = fma2v(qB4, Wg[4], agB0);  agB1 = fma2v(qB5, Wg[5], agB1);          \
    afB0 = fma2v(qB4, Wf[4], afB0);  afB1 = fma2v(qB5, Wf[5], afB1);          \
    aoB0 = fma2v(qB4, Wo[4], aoB0);  aoB1 = fma2v(qB5, Wo[5], aoB1);          \
    aiA0 = fma2v(qA6, Wi[6], aiA0);  aiA1 = fma2v(qA7, Wi[7], aiA1);          \
    agA0 = fma2v(qA6, Wg[6], agA0);  agA1 = fma2v(qA7, Wg[7], agA1);          \
    afA0 = fma2v(qA6, Wf[6], afA0);  afA1 = fma2v(qA7, Wf[7], afA1);          \
    aoA0 = fma2v(qA6, Wo[6], aoA0);  aoA1 = fma2v(qA7, Wo[7], aoA1);          \
    aiB0 = fma2v(qB6, Wi[6], aiB0);  aiB1 = fma2v(qB7, Wi[7], aiB1);          \
    agB0 = fma2v(qB6, Wg[6], agB0);  agB1 = fma2v(qB7, Wg[7], agB1);          \
    afB0 = fma2v(qB6, Wf[6], afB0);  afB1 = fma2v(qB7, Wf[7], afB1);          \
    aoB0 = fma2v(qB6, Wo[6], aoB0);  aoB1 = fma2v(qB7, Wo[7], aoB1);          \
    float lo_, hi_;                                                           \
    unpack2(lo_, hi_, add2(agA0, agA1)); float ggA = tanhapx(lo_ + hi_);      \
    unpack2(lo_, hi_, add2(agB0, agB1)); float ggB = tanhapx(lo_ + hi_);      \
    unpack2(lo_, hi_, add2(aiA0, aiA1)); float igA = fmaf(0.5f, tanhapx(lo_ + hi_), 0.5f); \
    unpack2(lo_, hi_, add2(aiB0, aiB1)); float igB = fmaf(0.5f, tanhapx(lo_ + hi_), 0.5f); \
    unpack2(lo_, hi_, add2(afA0, afA1)); float fgA = fmaf(0.5f, tanhapx(lo_ + hi_), 0.5f); \
    unpack2(lo_, hi_, add2(afB0, afB1)); float fgB = fmaf(0.5f, tanhapx(lo_ + hi_), 0.5f); \
    unpack2(lo_, hi_, add2(aoA0, aoA1)); float ogA = fmaf(0.5f, tanhapx(lo_ + hi_), 0.5f); \
    unpack2(lo_, hi_, add2(aoB0, aoB1)); float ogB = fmaf(0.5f, tanhapx(lo_ + hi_), 0.5f); \
    cA = fmaf(fgA, cA, igA * ggA);                                            \
    cB = fmaf(fgB, cB, igB * ggB);                                            \
    hA = ogA * tanhapx(cA);                                                   \
    hB = ogB * tanhapx(cB);                                                   \
} while (0)

__global__ __launch_bounds__(64, 1)
void lstm_decoder_kernel(
    const float* __restrict__ y,     // (B,16)
    const float* __restrict__ u,     // (B,128)
    const float* __restrict__ W_ih,  // (64,1)
    const float* __restrict__ W_hh,  // (64,16)
    const float* __restrict__ b_ih,  // (64)
    const float* __restrict__ b_hh,  // (64)
    const float* __restrict__ W_lin, // (1,16)
    const float* __restrict__ b_lin, // (1)
    const float* __restrict__ W_h0,  // (16,128)
    const float* __restrict__ b_h0,  // (16)
    const float* __restrict__ W_c0,  // (16,128)
    const float* __restrict__ b_c0,  // (16)
    float* __restrict__ out)         // (B,144)
{
    const int gid = blockIdx.x * 64 + threadIdx.x;
    const int grp = gid >> 4;        // 0..511: batch pair index
    const int j   = gid & 15;        // hidden index
    const int bA  = grp;             // first batch element
    const int bB  = grp + 512;       // second batch element
    const unsigned FULL = 0xffffffffu;

    // shared h buffer: 4 groups/block x 2 batch slots x 16 floats
    __shared__ __align__(16) float sh[8 * 16];
    uint32_t sbase;
    asm("{ .reg .u64 t; cvta.to.shared.u64 t, %1; cvt.u32.u64 %0, t; }"
        : "=r"(sbase) : "l"(sh));
    const int gb = threadIdx.x >> 4;                 // group in block (0..3)
    const uint32_t rdA = sbase + (gb * 2    ) * 64;  // slot A base
    const uint32_t rdB = sbase + (gb * 2 + 1) * 64;  // slot B base
    const uint32_t wrA = rdA + j * 4;
    const uint32_t wrB = rdB + j * 4;

    // ---- shared-per-thread gate-major packed weight pairs over k ----
    // i,f,o rows pre-scaled by 0.5 (sigmoid folding); g unscaled.
    uint64_t Wi[8], Wf[8], Wg[8], Wo[8];
#pragma unroll
    for (int p = 0; p < 8; p++) {
        Wi[p] = pack2(0.5f * W_hh[(     j) * 16 + 2*p], 0.5f * W_hh[(     j) * 16 + 2*p+1]);
        Wf[p] = pack2(0.5f * W_hh[(16 + j) * 16 + 2*p], 0.5f * W_hh[(16 + j) * 16 + 2*p+1]);
        Wg[p] = pack2(       W_hh[(32 + j) * 16 + 2*p],        W_hh[(32 + j) * 16 + 2*p+1]);
        Wo[p] = pack2(0.5f * W_hh[(48 + j) * 16 + 2*p], 0.5f * W_hh[(48 + j) * 16 + 2*p+1]);
    }
    const uint64_t wxi = pack2(0.5f * W_ih[j],      0.0f);
    const uint64_t wxf = pack2(0.5f * W_ih[16 + j], 0.0f);
    const uint64_t wxg = pack2(       W_ih[32 + j], 0.0f);
    const uint64_t wxo = pack2(0.5f * W_ih[48 + j], 0.0f);
    const uint64_t bvi = pack2(0.5f * (b_ih[j]      + b_hh[j]),      0.0f);
    const uint64_t bvf = pack2(0.5f * (b_ih[16 + j] + b_hh[16 + j]), 0.0f);
    const uint64_t bvg = pack2(       (b_ih[32 + j] + b_hh[32 + j]), 0.0f);
    const uint64_t bvo = pack2(0.5f * (b_ih[48 + j] + b_hh[48 + j]), 0.0f);
    const float wl = W_lin[j];
    const float bl = b_lin[0];

    // ---- h0/c0 for both batches (weight rows loaded once) ----
    float hA = b_h0[j], cA = b_c0[j];
    float hB = hA,      cB = cA;
    {
        const float4* uA4 = (const float4*)(u    + bA * 128);
        const float4* uB4 = (const float4*)(u    + bB * 128);
        const float4* wh4 = (const float4*)(W_h0 + j * 128);
        const float4* wc4 = (const float4*)(W_c0 + j * 128);
#pragma unroll 4
        for (int r = 0; r < 32; r++) {
            float4 ua = uA4[r], ub = uB4[r], wh = wh4[r], wc = wc4[r];
            hA = fmaf(ua.x, wh.x, hA); hA = fmaf(ua.y, wh.y, hA);
            hA = fmaf(ua.z, wh.z, hA); hA = fmaf(ua.w, wh.w, hA);
            cA = fmaf(ua.x, wc.x, cA); cA = fmaf(ua.y, wc.y, cA);
            cA = fmaf(ua.z, wc.z, cA); cA = fmaf(ua.w, wc.w, cA);
            hB = fmaf(ub.x, wh.x, hB); hB = fmaf(ub.y, wh.y, hB);
            hB = fmaf(ub.z, wh.z, hB); hB = fmaf(ub.w, wh.w, hB);
            cB = fmaf(ub.x, wc.x, cB); cB = fmaf(ub.y, wc.y, cB);
            cB = fmaf(ub.z, wc.z, cB); cB = fmaf(ub.w, wc.w, cB);
        }
    }

    // ---- windows replicated per-thread ----
    float xsA[16], xsB[16];
    {
        const float4* yA4 = (const float4*)(y + bA * 16);
        const float4* yB4 = (const float4*)(y + bB * 16);
#pragma unroll
        for (int q = 0; q < 4; q++) {
            float4 va = yA4[q], vb = yB4[q];
            xsA[4*q]=va.x; xsA[4*q+1]=va.y; xsA[4*q+2]=va.z; xsA[4*q+3]=va.w;
            xsB[4*q]=vb.x; xsB[4*q+1]=vb.y; xsB[4*q+2]=vb.z; xsB[4*q+3]=vb.w;
        }
    }
    out[bA * 144 + j] = y[bA * 16 + j];
    out[bB * 144 + j] = y[bB * 16 + j];
    float* outA = out + bA * 144 + 16;
    float* outB = out + bB * 144 + 16;

#pragma unroll 1
    for (int t = 0; t < NT; t++) {
#pragma unroll
        for (int s = 0; s < 16; s++) {
            CELL2(xsA[s], xsB[s]);
        }
        // preds for both batches; butterflies interleaved
        float pA = hA * wl, pB = hB * wl;
#pragma unroll
        for (int off = 8; off; off >>= 1) {
            pA += __shfl_xor_sync(FULL, pA, off, 16);
            pB += __shfl_xor_sync(FULL, pB, off, 16);
        }
        pA += bl; pB += bl;
        if (j == 0) { outA[t] = pA; outB[t] = pB; }
#pragma unroll
        for (int s = 0; s < 15; s++) { xsA[s] = xsA[s + 1]; xsB[s] = xsB[s + 1]; }
        xsA[15] = pA; xsB[15] = pB;
    }
}

extern "C" void kernel_launch(void* const* d_in, const int* in_sizes, int n_in,
                              void* d_out, int out_size) {
    const float* y     = (const float*)d_in[0];
    const float* u     = (const float*)d_in[1];
    const float* W_ih  = (const float*)d_in[2];
    const float* W_hh  = (const float*)d_in[3];
    const float* b_ih  = (const float*)d_in[4];
    const float* b_hh  = (const float*)d_in[5];
    const float* W_lin = (const float*)d_in[6];
    const float* b_lin = (const float*)d_in[7];
    const float* W_h0  = (const float*)d_in[8];
    const float* b_h0  = (const float*)d_in[9];
    const float* W_c0  = (const float*)d_in[10];
    const float* b_c0  = (const float*)d_in[11];
    float* out = (float*)d_out;

    lstm_decoder_kernel<<<128, 64>>>(y, u, W_ih, W_hh, b_ih, b_hh,
                                     W_lin, b_lin, W_h0, b_h0, W_c0, b_c0, out);
}

// round 14
// speedup vs baseline: 1.1576x; 1.1576x over previous
#include <cuda_runtime.h>
#include <cstdint>

// LSTMDecoder: B=1024, A=H=16, R=128, T=128.
// R13: gate-split across 32 lanes per batch element (one warp per batch).
//   lane = (p, j), p = lane>>4, j = lane&15.
//   p=0 computes gates i,f for hidden j; p=1 computes g,o.  32 scalar FFMA
//   per lane per cell -> per-warp fma issue span ~64 cyc (was 128).
//   Halves exchange raw gate sums via 2 parallel shfl_xor(16); both halves
//   redundantly run the nonlinear tail (no divergence, h on all lanes).
// 1024 warps = 512 blocks x 64 threads over 148 SMs (~1.7 warps/SMSP):
//   per-SMSP fma pipe ~111-128 cyc/cell = chip floor; co-resident warps hide
//   each other's serial tails (TLP, unlike R12's failed in-order ILP).
// Broadcast: sync-free SMEM STS->LDS.128 (validated R8). Sigmoid 0.5-scale
// folded into i,f,o weights/biases; scalar FFMA only (FFMA2 measured rt~4).

#define NT 128

__device__ __forceinline__ float tanhapx(float x) {
    float r;
    asm("tanh.approx.f32 %0, %1;" : "=f"(r) : "f"(x));
    return r;
}

__global__ __launch_bounds__(64, 1)
void lstm_decoder_kernel(
    const float* __restrict__ y,     // (B,16)
    const float* __restrict__ u,     // (B,128)
    const float* __restrict__ W_ih,  // (64,1)
    const float* __restrict__ W_hh,  // (64,16)
    const float* __restrict__ b_ih,  // (64)
    const float* __restrict__ b_hh,  // (64)
    const float* __restrict__ W_lin, // (1,16)
    const float* __restrict__ b_lin, // (1)
    const float* __restrict__ W_h0,  // (16,128)
    const float* __restrict__ b_h0,  // (16)
    const float* __restrict__ W_c0,  // (16,128)
    const float* __restrict__ b_c0,  // (16)
    float* __restrict__ out)         // (B,144)
{
    const int lane = threadIdx.x & 31;
    const int warp = threadIdx.x >> 5;          // 0..1
    const int b    = blockIdx.x * 2 + warp;     // batch element (one per warp)
    const int p    = lane >> 4;                 // gate-half: 0 -> i,f ; 1 -> g,o
    const int j    = lane & 15;                 // hidden index
    const unsigned FULL = 0xffffffffu;

    // shared h: 2 warps x 16 floats
    __shared__ __align__(16) float sh[2 * 16];
    uint32_t sbase;
    asm("{ .reg .u64 t; cvta.to.shared.u64 t, %1; cvt.u32.u64 %0, t; }"
        : "=r"(sbase) : "l"(sh));
    const uint32_t rdaddr = sbase + warp * 64;      // this warp's h vector
    const uint32_t wraddr = rdaddr + j * 4;         // h_j slot (both p write it)

    // ---- per-lane weights: 2 gate rows of W_hh ----
    // row0: i (p=0, scale 0.5) or g (p=1, scale 1); row1: f or o (scale 0.5).
    const int r0 = p ? (32 + j) : j;
    const int r1 = p ? (48 + j) : (16 + j);
    const float s0 = p ? 1.0f : 0.5f;

    float W0[16], W1[16];
#pragma unroll
    for (int k = 0; k < 16; k++) {
        W0[k] = s0   * W_hh[r0 * 16 + k];
        W1[k] = 0.5f * W_hh[r1 * 16 + k];
    }
    const float wx0 = s0   * W_ih[r0];
    const float wx1 = 0.5f * W_ih[r1];
    const float bv0 = s0   * (b_ih[r0] + b_hh[r0]);
    const float bv1 = 0.5f * (b_ih[r1] + b_hh[r1]);
    const float wl = W_lin[j];
    const float bl = b_lin[0];

    // ---- h0/c0 for this batch (computed redundantly on both halves) ----
    float h = b_h0[j];
    float c = b_c0[j];
    {
        const float4* u4  = (const float4*)(u    + b * 128);
        const float4* wh4 = (const float4*)(W_h0 + j * 128);
        const float4* wc4 = (const float4*)(W_c0 + j * 128);
#pragma unroll 4
        for (int r = 0; r < 32; r++) {
            float4 uu = u4[r], wh = wh4[r], wc = wc4[r];
            h = fmaf(uu.x, wh.x, h); h = fmaf(uu.y, wh.y, h);
            h = fmaf(uu.z, wh.z, h); h = fmaf(uu.w, wh.w, h);
            c = fmaf(uu.x, wc.x, c); c = fmaf(uu.y, wc.y, c);
            c = fmaf(uu.z, wc.z, c); c = fmaf(uu.w, wc.w, c);
        }
    }

    // ---- window replicated per-thread ----
    float xs[16];
    {
        const float4* y4 = (const float4*)(y + b * 16);
#pragma unroll
        for (int q = 0; q < 4; q++) {
            float4 v = y4[q];
            xs[4*q] = v.x; xs[4*q+1] = v.y; xs[4*q+2] = v.z; xs[4*q+3] = v.w;
        }
    }
    if (p == 0) out[b * 144 + j] = xs[0] * 0.0f + y[b * 16 + j];
    float* outp = out + b * 144 + 16;

#pragma unroll 1
    for (int t = 0; t < NT; t++) {
#pragma unroll
        for (int s = 0; s < 16; s++) {
            // publish h (both halves write identical value to sh[j]; benign)
            asm volatile("st.shared.f32 [%0], %1;" :: "r"(wraddr), "f"(h) : "memory");

            float xv = xs[s];
            // 4-way split chains for each of this lane's 2 gates
            float A0 = fmaf(xv, wx0, bv0), B0, C0, D0;
            float A1 = fmaf(xv, wx1, bv1), B1, C1, D1;

            float hv0, hv1, hv2, hv3, hv4, hv5, hv6, hv7;
            float hv8, hv9, hva, hvb, hvc, hvd, hve, hvf;
            asm volatile("ld.shared.v4.f32 {%0,%1,%2,%3}, [%4];"
                         : "=f"(hv0), "=f"(hv1), "=f"(hv2), "=f"(hv3)
                         : "r"(rdaddr) : "memory");
            asm volatile("ld.shared.v4.f32 {%0,%1,%2,%3}, [%4];"
                         : "=f"(hv4), "=f"(hv5), "=f"(hv6), "=f"(hv7)
                         : "r"(rdaddr + 16) : "memory");
            asm volatile("ld.shared.v4.f32 {%0,%1,%2,%3}, [%4];"
                         : "=f"(hv8), "=f"(hv9), "=f"(hva), "=f"(hvb)
                         : "r"(rdaddr + 32) : "memory");
            asm volatile("ld.shared.v4.f32 {%0,%1,%2,%3}, [%4];"
                         : "=f"(hvc), "=f"(hvd), "=f"(hve), "=f"(hvf)
                         : "r"(rdaddr + 48) : "memory");

            A0 = fmaf(hv0, W0[0], A0);   A1 = fmaf(hv0, W1[0], A1);
            B0 = hv1 * W0[1];            B1 = hv1 * W1[1];
            C0 = hv2 * W0[2];            C1 = hv2 * W1[2];
            D0 = hv3 * W0[3];            D1 = hv3 * W1[3];
            A0 = fmaf(hv4, W0[4], A0);   A1 = fmaf(hv4, W1[4], A1);
            B0 = fmaf(hv5, W0[5], B0);   B1 = fmaf(hv5, W1[5], B1);
            C0 = fmaf(hv6, W0[6], C0);   C1 = fmaf(hv6, W1[6], C1);
            D0 = fmaf(hv7, W0[7], D0);   D1 = fmaf(hv7, W1[7], D1);
            A0 = fmaf(hv8, W0[8], A0);   A1 = fmaf(hv8, W1[8], A1);
            B0 = fmaf(hv9, W0[9], B0);   B1 = fmaf(hv9, W1[9], B1);
            C0 = fmaf(hva, W0[10], C0);  C1 = fmaf(hva, W1[10], C1);
            D0 = fmaf(hvb, W0[11], D0);  D1 = fmaf(hvb, W1[11], D1);
            A0 = fmaf(hvc, W0[12], A0);  A1 = fmaf(hvc, W1[12], A1);
            B0 = fmaf(hvd, W0[13], B0);  B1 = fmaf(hvd, W1[13], B1);
            C0 = fmaf(hve, W0[14], C0);  C1 = fmaf(hve, W1[14], C1);
            D0 = fmaf(hvf, W0[15], D0);  D1 = fmaf(hvf, W1[15], D1);

            float a0 = (A0 + B0) + (C0 + D0);   // p=0: 0.5*ai ; p=1: ag
            float a1 = (A1 + B1) + (C1 + D1);   // p=0: 0.5*af ; p=1: 0.5*ao

            // exchange raw sums with the other gate-half (2 parallel hops)
            float o0 = __shfl_xor_sync(FULL, a0, 16);
            float o1 = __shfl_xor_sync(FULL, a1, 16);

            // reassemble per lane (both halves now have all four sums)
            float hai = p ? o0 : a0;    // 0.5*ai
            float haf = p ? o1 : a1;    // 0.5*af
            float agf = p ? a0 : o0;    // ag
            float hao = p ? a1 : o1;    // 0.5*ao

            // fg first (critical for c), then the rest
            float fg = fmaf(0.5f, tanhapx(haf), 0.5f);
            float gg = tanhapx(agf);
            float ig = fmaf(0.5f, tanhapx(hai), 0.5f);
            float og = fmaf(0.5f, tanhapx(hao), 0.5f);
            c = fmaf(fg, c, ig * gg);
            h = og * tanhapx(c);
        }
        // pred (h is on all 32 lanes; width-16 butterfly in each half)
        float pr = h * wl;
#pragma unroll
        for (int off = 8; off; off >>= 1)
            pr += __shfl_xor_sync(FULL, pr, off, 16);
        pr += bl;

        if (lane == 0) outp[t] = pr;
#pragma unroll
        for (int s = 0; s < 15; s++) xs[s] = xs[s + 1];
        xs[15] = pr;
    }
}

extern "C" void kernel_launch(void* const* d_in, const int* in_sizes, int n_in,
                              void* d_out, int out_size) {
    const float* y     = (const float*)d_in[0];
    const float* u     = (const float*)d_in[1];
    const float* W_ih  = (const float*)d_in[2];
    const float* W_hh  = (const float*)d_in[3];
    const float* b_ih  = (const float*)d_in[4];
    const float* b_hh  = (const float*)d_in[5];
    const float* W_lin = (const float*)d_in[6];
    const float* b_lin = (const float*)d_in[7];
    const float* W_h0  = (const float*)d_in[8];
    const float* b_h0  = (const float*)d_in[9];
    const float* W_c0  = (const float*)d_in[10];
    const float* b_c0  = (const float*)d_in[11];
    float* out = (float*)d_out;

    lstm_decoder_kernel<<<512, 64>>>(y, u, W_ih, W_hh, b_ih, b_hh,
                                     W_lin, b_lin, W_h0, b_h0, W_c0, b_c0, out);
}